// round 17
// baseline (speedup 1.0000x reference)
#include <cuda_runtime.h>
#include <cuda_bf16.h>
#include <cstdint>

// ---------------- problem constants ----------------
#define SEQ     4608
#define HIDDEN  1024
#define HEADS   16
#define DH      64
#define NTILES  36
#define TILE    128
#define NKV     27
#define HDIM    24
#define WDIM    24

// ---------------- device scratch ----------------
__device__ float g_q[HEADS * NTILES * TILE * DH];   // [h][n][r][d] tf32-rounded
__device__ float g_k[HEADS * NTILES * TILE * DH];   // [h][n][r][d] tf32-rounded
__device__ float g_v[HEADS * NTILES * DH * TILE];   // [h][n][d][r] transposed, tf32-rounded
__device__ unsigned short g_xh[SEQ * HIDDEN];
__device__ unsigned short g_xl[SEQ * HIDDEN];
__device__ unsigned short g_wh[4 * HIDDEN * HIDDEN];
__device__ unsigned short g_wl[4 * HIDDEN * HIDDEN];
__device__ unsigned short g_ah[SEQ * HIDDEN];
__device__ unsigned short g_al[SEQ * HIDDEN];

// ---------------- helpers ----------------
__device__ __forceinline__ float tf32r(float x) {
    uint32_t u;
    asm("cvt.rna.tf32.f32 %0, %1;" : "=r"(u) : "f"(x));
    return __uint_as_float(u);
}
__device__ __forceinline__ uint32_t fu(float x) { return __float_as_uint(x); }
__device__ __forceinline__ float ex2f(float x) {
    float r;
    asm("ex2.approx.f32 %0, %1;" : "=f"(r) : "f"(x));
    return r;
}
__device__ __forceinline__ uint32_t smem_u32(const void* p) {
    uint32_t a;
    asm("{ .reg .u64 t; cvta.to.shared.u64 t, %1; cvt.u32.u64 %0, t; }" : "=r"(a) : "l"(p));
    return a;
}
__device__ __forceinline__ void bsplit(float f, unsigned short& h, unsigned short& l) {
    __nv_bfloat16 hb = __float2bfloat16_rn(f);
    float fr = __bfloat162float(hb);
    __nv_bfloat16 lb = __float2bfloat16_rn(f - fr);
    h = reinterpret_cast<unsigned short&>(hb);
    l = reinterpret_cast<unsigned short&>(lb);
}

// tf32 m16n8k8 (attention)
__device__ __forceinline__ void mma8(float c[4],
                                     uint32_t a0, uint32_t a1, uint32_t a2, uint32_t a3,
                                     uint32_t b0, uint32_t b1)
{
    asm("mma.sync.aligned.m16n8k8.row.col.f32.tf32.tf32.f32 "
        "{%0,%1,%2,%3}, {%4,%5,%6,%7}, {%8,%9}, {%0,%1,%2,%3};"
        : "+f"(c[0]), "+f"(c[1]), "+f"(c[2]), "+f"(c[3])
        : "r"(a0), "r"(a1), "r"(a2), "r"(a3), "r"(b0), "r"(b1));
}
// bf16 m16n8k16 (projections)
__device__ __forceinline__ void mma16(float c[4], const uint32_t a[4],
                                      uint32_t b0, uint32_t b1)
{
    asm("mma.sync.aligned.m16n8k16.row.col.f32.bf16.bf16.f32 "
        "{%0,%1,%2,%3}, {%4,%5,%6,%7}, {%8,%9}, {%0,%1,%2,%3};"
        : "+f"(c[0]), "+f"(c[1]), "+f"(c[2]), "+f"(c[3])
        : "r"(a[0]), "r"(a[1]), "r"(a[2]), "r"(a[3]), "r"(b0), "r"(b1));
}

__device__ __forceinline__ void ldsm_x4(uint32_t r[4], uint32_t addr) {
    asm volatile("ldmatrix.sync.aligned.m8n8.x4.shared.b16 {%0,%1,%2,%3}, [%4];"
        : "=r"(r[0]), "=r"(r[1]), "=r"(r[2]), "=r"(r[3]) : "r"(addr));
}
__device__ __forceinline__ void ldsm_x2(uint32_t& r0, uint32_t& r1, uint32_t addr) {
    asm volatile("ldmatrix.sync.aligned.m8n8.x2.shared.b16 {%0,%1}, [%2];"
        : "=r"(r0), "=r"(r1) : "r"(addr));
}

#define CP_ASYNC16(dst, src) \
    asm volatile("cp.async.cg.shared.global [%0], [%1], 16;" :: "r"(dst), "l"(src) : "memory")
#define CP_COMMIT() asm volatile("cp.async.commit_group;" ::: "memory")
#define CP_WAIT(n)  asm volatile("cp.async.wait_group %0;" :: "n"(n) : "memory")

// =====================================================================
// Prep: split hidden_states + 4 weights into bf16 hi/lo globals.
// =====================================================================
#define XF4 (SEQ * HIDDEN / 4)
#define WF4 (HIDDEN * HIDDEN / 4)
#define PREP_BLOCKS ((XF4 + 4 * WF4) / 256)

__global__ __launch_bounds__(256)
void prep_split(const float* __restrict__ x,  const float* __restrict__ qw,
                const float* __restrict__ kw, const float* __restrict__ vw,
                const float* __restrict__ ow)
{
    int i4 = blockIdx.x * 256 + threadIdx.x;
    const float* src;
    unsigned short *dh, *dl;
    size_t off;
    if (i4 < XF4) {
        src = x; dh = g_xh; dl = g_xl; off = (size_t)i4 * 4;
    } else {
        int j = i4 - XF4;
        int seg = j / WF4;
        int o = j - seg * WF4;
        src = (seg == 0) ? qw : (seg == 1) ? kw : (seg == 2) ? vw : ow;
        dh = g_wh + (size_t)seg * HIDDEN * HIDDEN;
        dl = g_wl + (size_t)seg * HIDDEN * HIDDEN;
        off = (size_t)o * 4;
    }
    float4 v = *(const float4*)&src[off];
    unsigned short h0, h1, h2, h3, l0, l1, l2, l3;
    bsplit(v.x, h0, l0); bsplit(v.y, h1, l1);
    bsplit(v.z, h2, l2); bsplit(v.w, h3, l3);
    *(uint2*)&dh[off] = make_uint2((uint32_t)h0 | ((uint32_t)h1 << 16),
                                   (uint32_t)h2 | ((uint32_t)h3 << 16));
    *(uint2*)&dl[off] = make_uint2((uint32_t)l0 | ((uint32_t)l1 << 16),
                                   (uint32_t)l2 | ((uint32_t)l3 << 16));
}

// =====================================================================
// bf16 3-term GEMM, ldmatrix loads, term-major mma order:
// per k-step, all B frags staged in regs; three full (i,j) passes
// (hh, hl, lh) so dependent mmas on the same accumulator are 16 apart.
// Per-accumulator operand order unchanged -> bitwise-identical result.
// =====================================================================
#define GST  10240
#define GSTG 40960
#define GEMM_SMEM (2 * GSTG)

__global__ __launch_bounds__(256, 2)
void gemm_bf16(const unsigned short* __restrict__ Asrc_h,
               const unsigned short* __restrict__ Asrc_l,
               const unsigned short* __restrict__ Wh,
               const unsigned short* __restrict__ Wl,
               float* __restrict__ OutPlain, int mode)
{
    extern __shared__ char smc[];
    const int tid  = threadIdx.x;
    const int lane = tid & 31;
    const int wid  = tid >> 5;
    const int wm   = wid >> 2;
    const int wn   = wid & 3;
    const int qr   = lane >> 2;
    const int qc   = lane & 3;

    const int z  = blockIdx.z;
    const int m0 = blockIdx.y * 128;
    const int n0 = blockIdx.x * 128;
    const unsigned short* Bh = Wh + (size_t)z * HIDDEN * HIDDEN;
    const unsigned short* Bl = Wl + (size_t)z * HIDDEN * HIDDEN;

    const uint32_t smbase = smem_u32(smc);

    auto issue = [&](int kt, int s) {
        const int kb = kt * 32;
        const uint32_t sb = smbase + s * GSTG;
        const unsigned short* srcs[4] = {
            Asrc_h + (size_t)m0 * HIDDEN + kb,
            Asrc_l + (size_t)m0 * HIDDEN + kb,
            Bh + (size_t)n0 * HIDDEN + kb,
            Bl + (size_t)n0 * HIDDEN + kb };
#pragma unroll
        for (int arr = 0; arr < 4; arr++) {
#pragma unroll
            for (int half = 0; half < 2; half++) {
                int c = tid + half * 256;
                int row = c >> 2, part = c & 3;
                CP_ASYNC16(sb + arr * GST + row * 80 + part * 16,
                           srcs[arr] + (size_t)row * HIDDEN + part * 8);
            }
        }
        CP_COMMIT();
    };

    const uint32_t a_off = (uint32_t)((wm * 64 + ((lane >> 3) & 1) * 8 + (lane & 7)) * 80
                                      + ((lane >> 4) & 1) * 16);
    const uint32_t b_off = (uint32_t)((wn * 32 + (lane & 7)) * 80
                                      + ((lane >> 3) & 1) * 16);

    float c[4][4][4];
#pragma unroll
    for (int i = 0; i < 4; i++)
#pragma unroll
        for (int j = 0; j < 4; j++)
#pragma unroll
            for (int e = 0; e < 4; e++) c[i][j][e] = 0.f;

    issue(0, 0);

    for (int kt = 0; kt < HIDDEN / 32; kt++) {
        if (kt + 1 < HIDDEN / 32) { issue(kt + 1, (kt + 1) & 1); CP_WAIT(1); }
        else CP_WAIT(0);
        __syncthreads();

        const uint32_t st = smbase + (kt & 1) * GSTG;

#pragma unroll
        for (int ks = 0; ks < 2; ks++) {
            const uint32_t kso = ks * 32;
            uint32_t ah[4][4], al[4][4];
#pragma unroll
            for (int i = 0; i < 4; i++) {
                uint32_t aa = st + a_off + i * (16 * 80) + kso;
                ldsm_x4(ah[i], aa);
                ldsm_x4(al[i], aa + GST);
            }
            uint32_t bh[4][2], bl[4][2];
#pragma unroll
            for (int j = 0; j < 4; j++) {
                uint32_t ba = st + 2 * GST + b_off + j * (8 * 80) + kso;
                ldsm_x2(bh[j][0], bh[j][1], ba);
                ldsm_x2(bl[j][0], bl[j][1], ba + GST);
            }
            // term-major passes: dependent mmas on c[i][j] are 16 apart
#pragma unroll
            for (int i = 0; i < 4; i++)
#pragma unroll
                for (int j = 0; j < 4; j++)
                    mma16(c[i][j], ah[i], bh[j][0], bh[j][1]);
#pragma unroll
            for (int i = 0; i < 4; i++)
#pragma unroll
                for (int j = 0; j < 4; j++)
                    mma16(c[i][j], ah[i], bl[j][0], bl[j][1]);
#pragma unroll
            for (int i = 0; i < 4; i++)
#pragma unroll
                for (int j = 0; j < 4; j++)
                    mma16(c[i][j], al[i], bh[j][0], bh[j][1]);
        }
        __syncthreads();
    }

    // epilogue
#pragma unroll
    for (int i = 0; i < 4; i++) {
        int r0 = wm * 64 + i * 16 + qr;
#pragma unroll
        for (int half = 0; half < 2; half++) {
            int r = r0 + half * 8;
            int s = m0 + r;
            if (mode == 1) {
#pragma unroll
                for (int j = 0; j < 4; j++) {
                    int col = n0 + wn * 32 + j * 8 + qc * 2;
                    *(float2*)&OutPlain[(size_t)s * HIDDEN + col] =
                        make_float2(c[i][j][half * 2], c[i][j][half * 2 + 1]);
                }
            } else {
                int t = s / (HDIM * WDIM);
                int rem = s - t * (HDIM * WDIM);
                int h = rem / WDIM;
                int w2 = rem - h * WDIM;
                int n = ((t >> 1) * 3 + (h >> 3)) * 3 + (w2 >> 3);
                int rr = (((t & 1) << 3) + (h & 7)) * 8 + (w2 & 7);
#pragma unroll
                for (int j = 0; j < 4; j++) {
                    int o = n0 + wn * 32 + j * 8 + qc * 2;
                    int head = o >> 6;
                    int d = o & 63;
                    float p0 = tf32r(c[i][j][half * 2]);
                    float p1 = tf32r(c[i][j][half * 2 + 1]);
                    if (z == 2) {
                        float* dst = g_v + ((size_t)(head * NTILES + n) * DH + d) * TILE + rr;
                        dst[0] = p0;
                        dst[TILE] = p1;
                    } else {
                        float* dstm = z ? g_k : g_q;
                        *(float2*)&dstm[((size_t)(head * NTILES + n) * TILE + rr) * DH + d] =
                            make_float2(p0, p1);
                    }
                }
            }
        }
    }
}

// =====================================================================
// Attention: one CTA per (tile-PAIR, head). 3-stage cp.async ring,
// single sync per tile. QK loops reordered ks-major so sc[gr][j]
// accumulator reuse distance is 8 (was 2). Per-accumulator fp order
// unchanged (ks ascending) -> bitwise-identical result.
// =====================================================================
#define KP 72
#define VP 136
#define KROWB 288
#define KBYTES (128 * KROWB)            // 36864
#define VBYTES (64 * VP * 4)            // 34816
#define STAGE_B (KBYTES + VBYTES)       // 71680
#define ATTN_SMEM (3 * STAGE_B)         // 215040

__global__ __launch_bounds__(256, 1)
void attn_mma()
{
    extern __shared__ char smc[];
    const int p    = blockIdx.x;          // pair 0..17
    const int head = blockIdx.y;
    const int g    = p / 9;               // t-group: tc = g+1
    const int nh   = (p % 9) / 3;
    const int nw   = p % 3;
    const int tc   = g + 1;

    const int tid  = threadIdx.x;
    const int lane = tid & 31;
    const int wid  = tid >> 5;
    const int qr   = lane >> 2;
    const int qc   = lane & 3;
    const int tsel = wid >> 2;            // 0: nt=2g, 1: nt=2g+1
    const int rowbase = (wid & 3) * 32;   // 32 query rows per warp
    const int nt   = 2 * g + tsel;
    const int n    = (nt * 3 + nh) * 3 + nw;

    const uint32_t smbase = smem_u32(smc);

    auto issue = [&](int kt, int s) {
        int a = kt / 9, bb = (kt / 3) % 3, cc = kt % 3;
        int t = ((tc + a - 1) * 3 + bb) * 3 + cc;
        const uint32_t sb = smbase + s * STAGE_B;
        int row = tid >> 1, lh = (tid & 1) * 32;
        const float* ksrc = g_k + ((size_t)(head * NTILES + t) * TILE + row) * DH + lh;
        uint32_t kd = sb + row * KROWB + lh * 4;
#pragma unroll
        for (int i = 0; i < 8; i++) CP_ASYNC16(kd + i * 16, ksrc + i * 4);
        int d = tid >> 2, ko = (tid & 3) * 32;
        const float* vsrc = g_v + ((size_t)(head * NTILES + t) * DH + d) * TILE + ko;
        uint32_t vd = sb + KBYTES + d * (VP * 4) + ko * 4;
#pragma unroll
        for (int i = 0; i < 8; i++) CP_ASYNC16(vd + i * 16, vsrc + i * 4);
        CP_COMMIT();
    };

    issue(0, 0);
    issue(1, 1);

    // Q frags from gmem, 2 row-groups (sigma layout; scale*log2e folded)
    float2 qlo[2][8], qhi[2][8];
    {
        const float* qb = g_q + ((size_t)(head * NTILES + n) * TILE) * DH;
        const float qs = 0.125f * 1.44269504f;
#pragma unroll
        for (int gr = 0; gr < 2; gr++) {
#pragma unroll
            for (int ks = 0; ks < 8; ks++) {
                float2 a = *(const float2*)&qb[(rowbase + gr * 16 + qr) * DH + ks * 8 + 2 * qc];
                float2 b = *(const float2*)&qb[(rowbase + gr * 16 + qr + 8) * DH + ks * 8 + 2 * qc];
                qlo[gr][ks] = make_float2(tf32r(a.x * qs), tf32r(a.y * qs));
                qhi[gr][ks] = make_float2(tf32r(b.x * qs), tf32r(b.y * qs));
            }
        }
    }

    float oc[2][8][4];
#pragma unroll
    for (int gr = 0; gr < 2; gr++)
#pragma unroll
        for (int jo = 0; jo < 8; jo++)
#pragma unroll
            for (int e = 0; e < 4; e++) oc[gr][jo][e] = 0.f;
    float lsum[2][2] = {{0.f, 0.f}, {0.f, 0.f}};

    for (int kt = 0; kt < NKV; kt++) {
        if (kt + 1 < NKV) CP_WAIT(1);
        else CP_WAIT(0);
        __syncthreads();   // stage kt visible; also drains reads of stage (kt-1)%3
        if (kt + 2 < NKV) issue(kt + 2, (kt + 2) % 3);

        const char* Ks = smc + (kt % 3) * STAGE_B;
        const char* Vt = Ks + KBYTES;

#pragma unroll
        for (int q4 = 0; q4 < 4; q4++) {
            const int keyb = q4 * 32;
            float sc[2][4][4];
#pragma unroll
            for (int gr = 0; gr < 2; gr++)
#pragma unroll
                for (int j = 0; j < 4; j++)
#pragma unroll
                    for (int e = 0; e < 4; e++) sc[gr][j][e] = 0.f;

            // ks-major: sc[gr][j] accumulator reuse distance = 8 mmas
#pragma unroll
            for (int ks = 0; ks < 8; ks++) {
#pragma unroll
                for (int j = 0; j < 4; j++) {
                    float2 b2 = *(const float2*)(Ks +
                        (keyb + 8 * j + qr) * KROWB + (ks * 8 + 2 * qc) * 4);
                    uint32_t b0 = fu(b2.x), b1 = fu(b2.y);
                    mma8(sc[0][j], fu(qlo[0][ks].x), fu(qhi[0][ks].x),
                         fu(qlo[0][ks].y), fu(qhi[0][ks].y), b0, b1);
                    mma8(sc[1][j], fu(qlo[1][ks].x), fu(qhi[1][ks].x),
                         fu(qlo[1][ks].y), fu(qhi[1][ks].y), b0, b1);
                }
            }

#pragma unroll
            for (int j = 0; j < 4; j++) {
                uint32_t pa[2][4];
#pragma unroll
                for (int gr = 0; gr < 2; gr++) {
                    float p0 = ex2f(sc[gr][j][0]);
                    float p1 = ex2f(sc[gr][j][1]);
                    float p2 = ex2f(sc[gr][j][2]);
                    float p3 = ex2f(sc[gr][j][3]);
                    lsum[gr][0] += p0 + p1;
                    lsum[gr][1] += p2 + p3;
                    pa[gr][0] = fu(tf32r(p0)); pa[gr][1] = fu(tf32r(p2));
                    pa[gr][2] = fu(tf32r(p1)); pa[gr][3] = fu(tf32r(p3));
                }
                const int kb2 = (keyb + 8 * j + 2 * qc) * 4;
#pragma unroll
                for (int jo = 0; jo < 8; jo++) {
                    float2 v2 = *(const float2*)(Vt + (8 * jo + qr) * (VP * 4) + kb2);
                    uint32_t b0 = fu(v2.x), b1 = fu(v2.y);
                    mma8(oc[0][jo], pa[0][0], pa[0][1], pa[0][2], pa[0][3], b0, b1);
                    mma8(oc[1][jo], pa[1][0], pa[1][1], pa[1][2], pa[1][3], b0, b1);
                }
            }
        }
    }

    // reduce l across quad, normalize, untileize, bf16 hi/lo store
#pragma unroll
    for (int gr = 0; gr < 2; gr++) {
#pragma unroll
        for (int hh = 0; hh < 2; hh++) {
            float l = lsum[gr][hh];
            l += __shfl_xor_sync(0xffffffff, l, 1);
            l += __shfl_xor_sync(0xffffffff, l, 2);
            lsum[gr][hh] = 1.f / l;
        }
    }

#pragma unroll
    for (int gr = 0; gr < 2; gr++) {
#pragma unroll
        for (int half = 0; half < 2; half++) {
            int r = rowbase + gr * 16 + half * 8 + qr;
            float inv = lsum[gr][half];
            int it = r >> 6, ih = (r >> 3) & 7, iw = r & 7;
            int t = nt * 2 + it, h = nh * 8 + ih, w = nw * 8 + iw;
            int s = (t * HDIM + h) * WDIM + w;
            size_t base = (size_t)s * HIDDEN + head * DH;
#pragma unroll
            for (int jo = 0; jo < 8; jo++) {
                float f0 = oc[gr][jo][half * 2] * inv;
                float f1 = oc[gr][jo][half * 2 + 1] * inv;
                unsigned short h0, h1, lo0, lo1;
                bsplit(f0, h0, lo0);
                bsplit(f1, h1, lo1);
                *(uint32_t*)&g_ah[base + 8 * jo + 2 * qc] =
                    (uint32_t)h0 | ((uint32_t)h1 << 16);
                *(uint32_t*)&g_al[base + 8 * jo + 2 * qc] =
                    (uint32_t)lo0 | ((uint32_t)lo1 << 16);
            }
        }
    }
}

// ---------------- launch ----------------
extern "C" void kernel_launch(void* const* d_in, const int* in_sizes, int n_in,
                              void* d_out, int out_size)
{
    const float* x  = (const float*)d_in[0];
    const float* qw = (const float*)d_in[1];
    const float* kw = (const float*)d_in[2];
    const float* vw = (const float*)d_in[3];
    const float* ow = (const float*)d_in[4];
    float* out = (float*)d_out;
    (void)in_sizes; (void)n_in; (void)out_size;

    cudaFuncSetAttribute(gemm_bf16, cudaFuncAttributeMaxDynamicSharedMemorySize, GEMM_SMEM);
    cudaFuncSetAttribute(attn_mma, cudaFuncAttributeMaxDynamicSharedMemorySize, ATTN_SMEM);

    unsigned short *xh, *xl, *wh, *wl, *ah, *al;
    cudaGetSymbolAddress((void**)&xh, g_xh);
    cudaGetSymbolAddress((void**)&xl, g_xl);
    cudaGetSymbolAddress((void**)&wh, g_wh);
    cudaGetSymbolAddress((void**)&wl, g_wl);
    cudaGetSymbolAddress((void**)&ah, g_ah);
    cudaGetSymbolAddress((void**)&al, g_al);

    prep_split<<<PREP_BLOCKS, 256>>>(x, qw, kw, vw, ow);
    gemm_bf16<<<dim3(HIDDEN / 128, SEQ / 128, 3), 256, GEMM_SMEM>>>(xh, xl, wh, wl, nullptr, 0);
    attn_mma<<<dim3(18, HEADS), 256, ATTN_SMEM>>>();
    gemm_bf16<<<dim3(HIDDEN / 128, SEQ / 128, 1), 256, GEMM_SMEM>>>(
        ah, al, wh + (size_t)3 * HIDDEN * HIDDEN, wl + (size_t)3 * HIDDEN * HIDDEN, out, 1);
}